// round 3
// baseline (speedup 1.0000x reference)
#include <cuda_runtime.h>

// ---------------- problem constants ----------------
constexpr int BB   = 4;
constexpr int TT   = 2048;
constexpr int MM   = BB * TT;      // 8192 rows
constexpr int HS   = 1024;
constexpr int DK   = 512;
constexpr int DV   = 1024;
constexpr int IM   = 2816;
constexpr int RR   = 16;
constexpr int NH   = 4;
constexpr int DKH  = 128;          // per-head k dim
constexpr int DVH  = 256;          // per-head v dim
constexpr int CHK  = 64;
constexpr int NC   = TT / CHK;     // 32 chunks per batch
constexpr float GSCALE = 0.08838834764831845f; // dk^-0.5
constexpr float GEPS   = 1e-6f;
constexpr float GLNORM = 16.0f;

// ---------------- scratch (static device memory; no allocations) ----------------
// Aliasing plan (all in-place uses are same-thread read-then-write safe):
//   qe  overwrites q, kexp overwrites k, kd overwrites glog
//   og  overwrites o
//   nb  overwrites h
//   t2  overwrites t1
__device__ float g_h   [MM * HS];   // h, later nb
__device__ float g_q   [MM * DK];   // q, later qe
__device__ float g_k   [MM * DK];   // k, later kexp
__device__ float g_v   [MM * DV];
__device__ float g_gout[MM * DV];
__device__ float g_p16 [MM * RR];
__device__ float g_glog[MM * DK];   // glog, later kd
__device__ float g_ebl [BB * NH * NC * DKH];
__device__ float g_o   [MM * DV];   // o, later og
__device__ float g_x2  [MM * HS];
__device__ float g_t1  [MM * IM];   // t1, later t2

// ---------------- helpers ----------------
static __device__ __forceinline__ float block_reduce_sum(float v) {
    __shared__ float sh[32];
    int lane = threadIdx.x & 31;
    int wid  = threadIdx.x >> 5;
#pragma unroll
    for (int o = 16; o > 0; o >>= 1) v += __shfl_down_sync(0xffffffffu, v, o);
    if (lane == 0) sh[wid] = v;
    __syncthreads();
    int nw = (blockDim.x + 31) >> 5;
    if (wid == 0) {
        float r = (lane < nw) ? sh[lane] : 0.0f;
#pragma unroll
        for (int o = 16; o > 0; o >>= 1) r += __shfl_down_sync(0xffffffffu, r, o);
        if (lane == 0) sh[0] = r;
    }
    __syncthreads();
    return sh[0];
}

// ---------------- RMSNorm (row width = 1024) ----------------
__global__ void rms_kernel(const float* __restrict__ x, const float* __restrict__ w,
                           float* __restrict__ out, int width) {
    int row = blockIdx.x;
    const float* xr = x + (size_t)row * width;
    float ss = 0.f;
    for (int i = threadIdx.x; i < width; i += blockDim.x) { float v = xr[i]; ss += v * v; }
    float tot = block_reduce_sum(ss);
    float sc = rsqrtf(tot / (float)width + GEPS);
    float* orow = out + (size_t)row * width;
    for (int i = threadIdx.x; i < width; i += blockDim.x) orow[i] = xr[i] * sc * w[i];
}

// ---------------- SGEMM 128x128x16, 8x8 per thread, 256 threads ----------------
// EPI: 0 = C=AB ; 1 = C=AB+aux ; 2 = C = silu(aux) * (AB)
template <int EPI>
__global__ void __launch_bounds__(256)
sgemm_kernel(const float* __restrict__ A, const float* __restrict__ B,
             float* __restrict__ C, const float* __restrict__ aux,
             int M, int N, int K) {
    constexpr int BM = 128, BN = 128, BK = 16, TM = 8, TN = 8;
    __shared__ float As[BK * BM];
    __shared__ float Bs[BK * BN];
    int tid = threadIdx.x;
    int tx = tid & 15;   // 16 cols of threads
    int ty = tid >> 4;   // 16 rows of threads
    const float* Ablk = A + (size_t)blockIdx.y * BM * K;
    const float* Bblk = B + (size_t)blockIdx.x * BN;
    float acc[TM][TN];
#pragma unroll
    for (int i = 0; i < TM; i++)
#pragma unroll
        for (int j = 0; j < TN; j++) acc[i][j] = 0.f;

    for (int k0 = 0; k0 < K; k0 += BK) {
#pragma unroll
        for (int i = 0; i < 2; i++) {            // A tile: 128x16 -> 512 float4
            int idx = tid + i * 256;
            int row = idx >> 2;                  // /(BK/4)
            int c4  = idx & 3;
            float4 va = *(const float4*)(Ablk + (size_t)row * K + k0 + c4 * 4);
            As[(c4 * 4 + 0) * BM + row] = va.x;
            As[(c4 * 4 + 1) * BM + row] = va.y;
            As[(c4 * 4 + 2) * BM + row] = va.z;
            As[(c4 * 4 + 3) * BM + row] = va.w;
        }
#pragma unroll
        for (int i = 0; i < 2; i++) {            // B tile: 16x128 -> 512 float4
            int idx = tid + i * 256;
            int row = idx >> 5;                  // /(BN/4)
            int c4  = idx & 31;
            *(float4*)(&Bs[row * BN + c4 * 4]) =
                *(const float4*)(Bblk + (size_t)(k0 + row) * N + c4 * 4);
        }
        __syncthreads();
#pragma unroll
        for (int kk = 0; kk < BK; kk++) {
            float ra[TM], rb[TN];
#pragma unroll
            for (int i = 0; i < TM; i++) ra[i] = As[kk * BM + ty * TM + i];
#pragma unroll
            for (int j = 0; j < TN; j++) rb[j] = Bs[kk * BN + tx * TN + j];
#pragma unroll
            for (int i = 0; i < TM; i++)
#pragma unroll
                for (int j = 0; j < TN; j++) acc[i][j] += ra[i] * rb[j];
        }
        __syncthreads();
    }
#pragma unroll
    for (int i = 0; i < TM; i++) {
        int r = blockIdx.y * BM + ty * TM + i;
#pragma unroll
        for (int j = 0; j < TN; j++) {
            int c = blockIdx.x * BN + tx * TN + j;
            size_t oi = (size_t)r * N + c;
            float v = acc[i][j];
            if (EPI == 1) v += aux[oi];
            if (EPI == 2) { float g = aux[oi]; v *= g / (1.f + __expf(-g)); }
            C[oi] = v;
        }
    }
}

// ---------------- low-rank gate path ----------------
__global__ void p16_kernel(const float* __restrict__ h, const float* __restrict__ Wgk1,
                           float* __restrict__ p16) {
    int row = blockIdx.x;
    int tid = threadIdx.x;                 // 128 threads
    float acc[RR];
#pragma unroll
    for (int r = 0; r < RR; r++) acc[r] = 0.f;
    const float* hr = h + (size_t)row * HS;
    for (int kk = tid; kk < HS; kk += 128) {
        float hv = hr[kk];
        const float* w = Wgk1 + (size_t)kk * RR;
#pragma unroll
        for (int r = 0; r < RR; r++) acc[r] += hv * w[r];
    }
    __shared__ float red[128 * RR];
#pragma unroll
    for (int r = 0; r < RR; r++) red[tid * RR + r] = acc[r];
    __syncthreads();
    for (int off = 64; off > 0; off >>= 1) {
        if (tid < off) {
#pragma unroll
            for (int r = 0; r < RR; r++) red[tid * RR + r] += red[(tid + off) * RR + r];
        }
        __syncthreads();
    }
    if (tid < RR) p16[(size_t)row * RR + tid] = red[tid];
}

__global__ void glog_kernel(const float* __restrict__ p16, const float* __restrict__ Wgk2,
                            const float* __restrict__ bgk2, float* __restrict__ glog) {
    int row = blockIdx.x;
    int tid = threadIdx.x;                 // 256 threads
    __shared__ float ps[RR];
    if (tid < RR) ps[tid] = p16[(size_t)row * RR + tid];
    __syncthreads();
    for (int n = tid; n < DK; n += 256) {
        float acc = bgk2[n];
#pragma unroll
        for (int r = 0; r < RR; r++) acc += ps[r] * Wgk2[r * DK + n];
        float x = acc;
        float ls = fminf(x, 0.f) - log1pf(expf(-fabsf(x)));
        glog[(size_t)row * DK + n] = ls / GLNORM;
    }
}

// ---------------- GLA precompute: b-cumsum, qe, kexp, kd, e^{b_last} ----------------
// In-place: qe aliases q, kexp aliases k, kd aliases glog (same-index read->write).
__global__ void gla_pre_kernel(float* __restrict__ q, float* __restrict__ k,
                               float* __restrict__ glog,
                               float* __restrict__ ebl) {
    int cid = blockIdx.x;                       // (b*NH + h)*NC + n
    int n = cid % NC;
    int hh = (cid / NC) % NH;
    int b = cid / (NC * NH);
    int d = threadIdx.x;                        // 128
    __shared__ float bsm[CHK * DKH];
    int base = b * TT + n * CHK;
    int col = hh * DKH + d;
    float bs = 0.f;
    for (int c = 0; c < CHK; c++) {
        bs += glog[(size_t)(base + c) * DK + col];
        bsm[c * DKH + d] = bs;
    }
    float blast = bs;
    ebl[(size_t)cid * DKH + d] = expf(blast);
    for (int c = 0; c < CHK; c++) {
        float bb = bsm[c * DKH + d];
        size_t idx = (size_t)(base + c) * DK + col;
        float qv = q[idx], kv = k[idx];
        q[idx]    = qv * expf(bb) * GSCALE;      // qe
        k[idx]    = kv * expf(-bb);              // kexp
        glog[idx] = kv * expf(blast - bb);       // kd
    }
}

// ---------------- GLA intra-chunk: A = tril(qe kexp^T); o = A v ----------------
__global__ void __launch_bounds__(256)
gla_intra_kernel(const float* __restrict__ qe, const float* __restrict__ ke,
                 const float* __restrict__ v, float* __restrict__ o) {
    extern __shared__ float sm[];
    float* qs = sm;                 // 64*128
    float* ks = sm + CHK * DKH;     // 64*128
    float* Am = ks + CHK * DKH;     // 64*64
    int cid = blockIdx.x;
    int n = cid % NC;
    int hh = (cid / NC) % NH;
    int b = cid / (NC * NH);
    int tid = threadIdx.x;          // 256
    int base = b * TT + n * CHK;
    int colb = hh * DKH;
#pragma unroll
    for (int i = 0; i < 8; i++) {   // 2048 float4 each, 256 threads
        int idx4 = tid + i * 256;
        int c = idx4 >> 5;
        int d4 = idx4 & 31;
        *(float4*)(qs + c * DKH + d4 * 4) =
            *(const float4*)(qe + (size_t)(base + c) * DK + colb + d4 * 4);
        *(float4*)(ks + c * DKH + d4 * 4) =
            *(const float4*)(ke + (size_t)(base + c) * DK + colb + d4 * 4);
    }
    __syncthreads();
#pragma unroll
    for (int i = 0; i < 16; i++) {  // 4096 entries of A
        int idx = tid + i * 256;
        int c = idx >> 6;
        int s = idx & 63;
        float a = 0.f;
        if (s <= c) {
#pragma unroll 8
            for (int d = 0; d < DKH; d++) a += qs[c * DKH + d] * ks[s * DKH + d];
        }
        Am[c * CHK + s] = a;
    }
    __syncthreads();
    // o[c][e] for e = tid (256 v-cols of this head)
    float accv[CHK];
#pragma unroll
    for (int c = 0; c < CHK; c++) accv[c] = 0.f;
    int gcol = hh * DVH + tid;
    for (int s = 0; s < CHK; s++) {
        float vv = v[(size_t)(base + s) * DV + gcol];
#pragma unroll
        for (int c = 0; c < CHK; c++) accv[c] += Am[c * CHK + s] * vv;
    }
#pragma unroll
    for (int c = 0; c < CHK; c++) o[(size_t)(base + c) * DV + gcol] = accv[c];
}

// ---------------- GLA inter-chunk scan (serial over chunks; dv-sliced) ----------------
constexpr int NSL = 16;       // slices of dv
constexpr int SLW = DVH / NSL; // 16 columns per slice
__global__ void __launch_bounds__(128)
gla_scan_kernel(const float* __restrict__ qe, const float* __restrict__ kd,
                const float* __restrict__ v, const float* __restrict__ ebl,
                float* __restrict__ o) {
    extern __shared__ float sm[];
    float* qs  = sm;                        // 64*128
    float* kds = qs + CHK * DKH;            // 64*128
    float* vs  = kds + CHK * DKH;           // 64*16
    float* S   = vs + CHK * SLW;            // 128*16
    float* eb  = S + DKH * SLW;             // 128
    int bi = blockIdx.x;
    int sl = bi % NSL;
    int bh = bi / NSL;
    int hh = bh % NH;
    int b  = bh / NH;
    int tid = threadIdx.x;                  // 128
    for (int i = tid; i < DKH * SLW; i += 128) S[i] = 0.f;
    int e0 = hh * DVH + sl * SLW;
    for (int n = 0; n < NC; n++) {
        int cid = (b * NH + hh) * NC + n;
        int base = b * TT + n * CHK;
        int colb = hh * DKH;
#pragma unroll
        for (int i = 0; i < 16; i++) {
            int idx4 = tid + i * 128;
            int c = idx4 >> 5;
            int d4 = idx4 & 31;
            *(float4*)(qs + c * DKH + d4 * 4) =
                *(const float4*)(qe + (size_t)(base + c) * DK + colb + d4 * 4);
            *(float4*)(kds + c * DKH + d4 * 4) =
                *(const float4*)(kd + (size_t)(base + c) * DK + colb + d4 * 4);
        }
#pragma unroll
        for (int i = 0; i < 8; i++) {
            int idx = tid + i * 128;
            int c = idx / SLW;
            int e = idx % SLW;
            vs[idx] = v[(size_t)(base + c) * DV + e0 + e];
        }
        eb[tid] = ebl[(size_t)cid * DKH + tid];
        __syncthreads();
        // o_inter += qe_c @ S  (use pre-update S)
#pragma unroll
        for (int i = 0; i < 8; i++) {
            int idx = tid + i * 128;
            int c = idx / SLW;
            int e = idx % SLW;
            float a = 0.f;
#pragma unroll 8
            for (int d = 0; d < DKH; d++) a += qs[c * DKH + d] * S[d * SLW + e];
            size_t oi = (size_t)(base + c) * DV + e0 + e;
            o[oi] += a;
        }
        __syncthreads();
        // S = S * e^{blast} + kd^T @ v
#pragma unroll
        for (int i = 0; i < 16; i++) {
            int idx = tid + i * 128;
            int d = idx / SLW;
            int e = idx % SLW;
            float s = S[idx] * eb[d];
#pragma unroll 8
            for (int c = 0; c < CHK; c++) s += kds[c * DKH + d] * vs[c * SLW + e];
            S[idx] = s;
        }
        __syncthreads();
    }
}

// ---------------- gated head-RMSNorm: og = rms(o)*gnorm_w * silu(gout) ----------------
// In-place: og aliases o (all reads of this block's o-slice complete before the
// block reduction barrier; writes happen after).
__global__ void gate_kernel(float* __restrict__ o, const float* __restrict__ gout,
                            const float* __restrict__ gw) {
    int bi = blockIdx.x;            // B*T*NH
    int bt = bi >> 2;
    int hh = bi & 3;
    int e = threadIdx.x;            // 256
    size_t idx = (size_t)bt * DV + hh * DVH + e;
    float ov = o[idx];
    float tot = block_reduce_sum(ov * ov);
    float sc = rsqrtf(tot / (float)DVH + GEPS);
    float g = gout[idx];
    o[idx] = ov * sc * gw[e] * (g / (1.f + expf(-g)));
}

// ---------------- host orchestration ----------------
static void launch_sgemm(int epi, const float* A, const float* B, float* C,
                         const float* aux, int M, int N, int K) {
    dim3 grid(N / 128, M / 128);
    if (epi == 0)      sgemm_kernel<0><<<grid, 256>>>(A, B, C, aux, M, N, K);
    else if (epi == 1) sgemm_kernel<1><<<grid, 256>>>(A, B, C, aux, M, N, K);
    else               sgemm_kernel<2><<<grid, 256>>>(A, B, C, aux, M, N, K);
}

extern "C" void kernel_launch(void* const* d_in, const int* in_sizes, int n_in,
                              void* d_out, int out_size) {
    const float* x      = (const float*)d_in[0];
    const float* anw    = (const float*)d_in[1];
    const float* Wq     = (const float*)d_in[2];
    const float* Wk     = (const float*)d_in[3];
    const float* Wv     = (const float*)d_in[4];
    const float* Wg     = (const float*)d_in[5];
    const float* Wgk1   = (const float*)d_in[6];
    const float* Wgk2   = (const float*)d_in[7];
    const float* bgk2   = (const float*)d_in[8];
    const float* gnw    = (const float*)d_in[9];
    const float* Wo     = (const float*)d_in[10];
    const float* mnw    = (const float*)d_in[11];
    const float* Wgate  = (const float*)d_in[12];
    const float* Wup    = (const float*)d_in[13];
    const float* Wdown  = (const float*)d_in[14];
    float* out = (float*)d_out;

    float *h, *q, *k, *v, *gout, *p16, *glog, *ebl, *o, *x2, *t1;
    cudaGetSymbolAddress((void**)&h,    g_h);
    cudaGetSymbolAddress((void**)&q,    g_q);
    cudaGetSymbolAddress((void**)&k,    g_k);
    cudaGetSymbolAddress((void**)&v,    g_v);
    cudaGetSymbolAddress((void**)&gout, g_gout);
    cudaGetSymbolAddress((void**)&p16,  g_p16);
    cudaGetSymbolAddress((void**)&glog, g_glog);
    cudaGetSymbolAddress((void**)&ebl,  g_ebl);
    cudaGetSymbolAddress((void**)&o,    g_o);
    cudaGetSymbolAddress((void**)&x2,   g_x2);
    cudaGetSymbolAddress((void**)&t1,   g_t1);

    // Aliases (documented in-place reuse)
    float* qe   = q;
    float* kexp = k;
    float* kd   = glog;
    float* og   = o;
    float* nb   = h;
    float* t2   = t1;

    int intra_smem = (CHK * DKH * 2 + CHK * CHK) * 4;                      // 81920 B
    int scan_smem  = (CHK * DKH * 2 + CHK * SLW + DKH * SLW + DKH) * 4;    // 78336 B
    cudaFuncSetAttribute(gla_intra_kernel, cudaFuncAttributeMaxDynamicSharedMemorySize, intra_smem);
    cudaFuncSetAttribute(gla_scan_kernel,  cudaFuncAttributeMaxDynamicSharedMemorySize, scan_smem);

    // 1) attn norm
    rms_kernel<<<MM, 256>>>(x, anw, h, HS);
    // 2) projections
    launch_sgemm(0, h, Wq, q,    nullptr, MM, DK, HS);
    launch_sgemm(0, h, Wk, k,    nullptr, MM, DK, HS);
    launch_sgemm(0, h, Wv, v,    nullptr, MM, DV, HS);
    launch_sgemm(0, h, Wg, gout, nullptr, MM, DV, HS);
    // 3) gate logits (low rank)
    p16_kernel<<<MM, 128>>>(h, Wgk1, p16);
    glog_kernel<<<MM, 256>>>(p16, Wgk2, bgk2, glog);
    // 4) GLA (gla_pre converts q->qe, k->kexp, glog->kd in place)
    gla_pre_kernel<<<BB * NH * NC, DKH>>>(q, k, glog, ebl);
    gla_intra_kernel<<<BB * NH * NC, 256, intra_smem>>>(qe, kexp, v, o);
    gla_scan_kernel<<<BB * NH * NSL, DKH, scan_smem>>>(qe, kd, v, ebl, o);
    // 5) gated head norm (o -> og in place)
    gate_kernel<<<MM * NH, DVH>>>(o, gout, gnw);
    // 6) output projection + residual -> x2
    launch_sgemm(1, og, Wo, x2, x, MM, HS, DV);
    // 7) MLP (nb aliases h; t2 aliases t1)
    rms_kernel<<<MM, 256>>>(x2, mnw, nb, HS);
    launch_sgemm(0, nb, Wgate, t1, nullptr, MM, IM, HS);
    launch_sgemm(2, nb, Wup,   t2, t1,      MM, IM, HS);   // t2 = silu(t1) * (nb@Wup)
    launch_sgemm(1, t2, Wdown, out, x2,     MM, HS, IM);   // out = x2 + t2@Wdown
}

// round 6
// speedup vs baseline: 2.0028x; 2.0028x over previous
#include <cuda_runtime.h>
#include <cstdint>

// ---------------- problem constants ----------------
constexpr int BB   = 4;
constexpr int TT   = 2048;
constexpr int MM   = BB * TT;      // 8192 rows
constexpr int HS   = 1024;
constexpr int DK   = 512;
constexpr int DV   = 1024;
constexpr int IM   = 2816;
constexpr int RR   = 16;
constexpr int NH   = 4;
constexpr int DKH  = 128;          // per-head k dim
constexpr int DVH  = 256;          // per-head v dim
constexpr int CHK  = 64;
constexpr int NC   = TT / CHK;     // 32 chunks per batch
constexpr float GSCALE = 0.08838834764831845f; // dk^-0.5
constexpr float GEPS   = 1e-6f;
constexpr float GLNORM = 16.0f;

// ---------------- scratch (static device memory; no allocations) ----------------
__device__ float g_h   [MM * HS];   // h, later nb
__device__ float g_q   [MM * DK];   // q, later qe
__device__ float g_k   [MM * DK];   // k, later kexp
__device__ float g_v   [MM * DV];
__device__ float g_gout[MM * DV];
__device__ float g_p16 [MM * RR];
__device__ float g_glog[MM * DK];   // glog, later kd
__device__ float g_ebl [BB * NH * NC * DKH];
__device__ float g_o   [MM * DV];   // o, later og
__device__ float g_x2  [MM * HS];
__device__ float g_t1  [MM * IM];   // t1, later t2

// ---------------- helpers ----------------
static __device__ __forceinline__ float block_reduce_sum(float v) {
    __shared__ float sh[32];
    int lane = threadIdx.x & 31;
    int wid  = threadIdx.x >> 5;
#pragma unroll
    for (int o = 16; o > 0; o >>= 1) v += __shfl_down_sync(0xffffffffu, v, o);
    if (lane == 0) sh[wid] = v;
    __syncthreads();
    int nw = (blockDim.x + 31) >> 5;
    if (wid == 0) {
        float r = (lane < nw) ? sh[lane] : 0.0f;
#pragma unroll
        for (int o = 16; o > 0; o >>= 1) r += __shfl_down_sync(0xffffffffu, r, o);
        if (lane == 0) sh[0] = r;
    }
    __syncthreads();
    return sh[0];
}

static __device__ __forceinline__ uint32_t f2tf(float f) {
    uint32_t u;
    asm("cvt.rna.tf32.f32 %0, %1;" : "=r"(u) : "f"(f));
    return u;
}

// ---------------- RMSNorm (row width = 1024) ----------------
__global__ void rms_kernel(const float* __restrict__ x, const float* __restrict__ w,
                           float* __restrict__ out, int width) {
    int row = blockIdx.x;
    const float* xr = x + (size_t)row * width;
    float ss = 0.f;
    for (int i = threadIdx.x; i < width; i += blockDim.x) { float v = xr[i]; ss += v * v; }
    float tot = block_reduce_sum(ss);
    float sc = rsqrtf(tot / (float)width + GEPS);
    float* orow = out + (size_t)row * width;
    for (int i = threadIdx.x; i < width; i += blockDim.x) orow[i] = xr[i] * sc * w[i];
}

// ---------------- TF32 tensor-core GEMM ----------------
// 128x128x32 CTA tile, 8 warps (4M x 2N), warp tile 32x64 (2x8 m16n8k8).
// Double-buffered smem with register staging; fp32 accumulate.
// EPI: 0 = C=AB ; 1 = C=AB+aux ; 2 = C = silu(aux) * (AB)
template <int EPI>
__global__ void __launch_bounds__(256)
tgemm_kernel(const float* __restrict__ A, const float* __restrict__ B,
             float* __restrict__ C, const float* __restrict__ aux,
             int M, int N, int K) {
    constexpr int BM = 128, BN = 128, BK = 32;
    constexpr int AST = BK + 4;   // 36: A stored [BM][AST] (row-major, padded)
    constexpr int BST = BN + 8;   // 136: B stored [BK][BST]
    extern __shared__ uint32_t smx[];
    uint32_t* As = smx;                    // 2 * BM*AST
    uint32_t* Bs = smx + 2 * BM * AST;     // 2 * BK*BST

    const int tid   = threadIdx.x;
    const int lane  = tid & 31;
    const int warp  = tid >> 5;
    const int warpM = warp & 3;      // 0..3
    const int warpN = warp >> 2;     // 0..1
    const int g     = lane >> 2;     // groupID 0..7
    const int tg    = lane & 3;      // threadID_in_group 0..3

    // B producer mapping (coalesced gmem + conflict-free STS.128)
    const int bsub   = tid & 3;          // word-quad within chunk
    const int bchunk = (tid >> 2) & 7;   // 16-float chunk
    const int bw     = tid >> 5;         // 0..7 -> krows 4*bw+j

    const size_t arow0 = (size_t)blockIdx.y * BM;
    const size_t bcol0 = (size_t)blockIdx.x * BN;

    float4 ar[4], br[4];

    auto LDG = [&](int k0) {
#pragma unroll
        for (int j = 0; j < 4; j++) {          // A: f = j*256+tid -> row=f>>3, kq=f&7
            int f = j * 256 + tid;
            int row = f >> 3, kq = f & 7;
            ar[j] = *(const float4*)(A + (arow0 + row) * K + k0 + kq * 4);
        }
#pragma unroll
        for (int j = 0; j < 4; j++) {
            int krow = 4 * bw + j;
            br[j] = *(const float4*)(B + (size_t)(k0 + krow) * N + bcol0 + bchunk * 16 + bsub * 4);
        }
    };
    auto STS = [&](int buf) {
        uint32_t* Ab = As + buf * (BM * AST);
#pragma unroll
        for (int j = 0; j < 4; j++) {
            int f = j * 256 + tid;
            int row = f >> 3, kq = f & 7;
            uint4 t;
            t.x = f2tf(ar[j].x); t.y = f2tf(ar[j].y);
            t.z = f2tf(ar[j].z); t.w = f2tf(ar[j].w);
            *(uint4*)(Ab + row * AST + kq * 4) = t;
        }
        uint32_t* Bb = Bs + buf * (BK * BST);
#pragma unroll
        for (int j = 0; j < 4; j++) {
            int krow = 4 * bw + j;
            uint4 t;
            t.x = f2tf(br[j].x); t.y = f2tf(br[j].y);
            t.z = f2tf(br[j].z); t.w = f2tf(br[j].w);
            *(uint4*)(Bb + krow * BST + bchunk * 16 + bsub * 4) = t;
        }
    };

    float acc[2][8][4];
#pragma unroll
    for (int mt = 0; mt < 2; mt++)
#pragma unroll
        for (int nt = 0; nt < 8; nt++)
#pragma unroll
            for (int i = 0; i < 4; i++) acc[mt][nt][i] = 0.f;

    LDG(0);
    STS(0);
    __syncthreads();

    const int nIter = K / BK;
    int buf = 0;
    for (int it = 0; it < nIter; ++it) {
        if (it + 1 < nIter) LDG((it + 1) * BK);
        const uint32_t* Ab = As + buf * (BM * AST);
        const uint32_t* Bb = Bs + buf * (BK * BST);
#pragma unroll
        for (int ks = 0; ks < 4; ++ks) {
            uint32_t af[2][4], bf[8][2];
            int kc = ks * 8 + tg;
#pragma unroll
            for (int mt = 0; mt < 2; ++mt) {
                int r = warpM * 32 + mt * 16 + g;
                af[mt][0] = Ab[r * AST + kc];
                af[mt][1] = Ab[(r + 8) * AST + kc];
                af[mt][2] = Ab[r * AST + kc + 4];
                af[mt][3] = Ab[(r + 8) * AST + kc + 4];
            }
#pragma unroll
            for (int nt = 0; nt < 8; ++nt) {
                int c = warpN * 64 + nt * 8 + g;
                bf[nt][0] = Bb[kc * BST + c];
                bf[nt][1] = Bb[(kc + 4) * BST + c];
            }
#pragma unroll
            for (int mt = 0; mt < 2; ++mt)
#pragma unroll
                for (int nt = 0; nt < 8; ++nt) {
                    asm volatile(
                        "mma.sync.aligned.m16n8k8.row.col.f32.tf32.tf32.f32 "
                        "{%0,%1,%2,%3},{%4,%5,%6,%7},{%8,%9},{%0,%1,%2,%3};"
                        : "+f"(acc[mt][nt][0]), "+f"(acc[mt][nt][1]),
                          "+f"(acc[mt][nt][2]), "+f"(acc[mt][nt][3])
                        : "r"(af[mt][0]), "r"(af[mt][1]), "r"(af[mt][2]), "r"(af[mt][3]),
                          "r"(bf[nt][0]), "r"(bf[nt][1]));
                }
        }
        if (it + 1 < nIter) STS(buf ^ 1);
        __syncthreads();
        buf ^= 1;
    }

    // epilogue
    int r0b = blockIdx.y * BM + warpM * 32 + g;
    int cb  = blockIdx.x * BN + warpN * 64;
#pragma unroll
    for (int mt = 0; mt < 2; ++mt) {
        int r0 = r0b + mt * 16;
#pragma unroll
        for (int nt = 0; nt < 8; ++nt) {
            int c = cb + nt * 8 + tg * 2;
            size_t i0 = (size_t)r0 * N + c;
            size_t i1 = (size_t)(r0 + 8) * N + c;
            float v0 = acc[mt][nt][0], v1 = acc[mt][nt][1];
            float v2 = acc[mt][nt][2], v3 = acc[mt][nt][3];
            if (EPI == 1) {
                v0 += aux[i0]; v1 += aux[i0 + 1];
                v2 += aux[i1]; v3 += aux[i1 + 1];
            }
            if (EPI == 2) {
                float a0 = aux[i0], a1 = aux[i0 + 1], a2 = aux[i1], a3 = aux[i1 + 1];
                v0 *= a0 / (1.f + __expf(-a0));
                v1 *= a1 / (1.f + __expf(-a1));
                v2 *= a2 / (1.f + __expf(-a2));
                v3 *= a3 / (1.f + __expf(-a3));
            }
            float2 p0 = make_float2(v0, v1);
            float2 p1 = make_float2(v2, v3);
            *(float2*)(C + i0) = p0;
            *(float2*)(C + i1) = p1;
        }
    }
}

constexpr int TG_SMEM = (2 * 128 * 36 + 2 * 32 * 136) * 4;  // 71680 B

// ---------------- low-rank gate path ----------------
__global__ void p16_kernel(const float* __restrict__ h, const float* __restrict__ Wgk1,
                           float* __restrict__ p16) {
    int row = blockIdx.x;
    int tid = threadIdx.x;                 // 128 threads
    float acc[RR];
#pragma unroll
    for (int r = 0; r < RR; r++) acc[r] = 0.f;
    const float* hr = h + (size_t)row * HS;
    for (int kk = tid; kk < HS; kk += 128) {
        float hv = hr[kk];
        const float* w = Wgk1 + (size_t)kk * RR;
#pragma unroll
        for (int r = 0; r < RR; r++) acc[r] += hv * w[r];
    }
    __shared__ float red[128 * RR];
#pragma unroll
    for (int r = 0; r < RR; r++) red[tid * RR + r] = acc[r];
    __syncthreads();
    for (int off = 64; off > 0; off >>= 1) {
        if (tid < off) {
#pragma unroll
            for (int r = 0; r < RR; r++) red[tid * RR + r] += red[(tid + off) * RR + r];
        }
        __syncthreads();
    }
    if (tid < RR) p16[(size_t)row * RR + tid] = red[tid];
}

__global__ void glog_kernel(const float* __restrict__ p16, const float* __restrict__ Wgk2,
                            const float* __restrict__ bgk2, float* __restrict__ glog) {
    int row = blockIdx.x;
    int tid = threadIdx.x;                 // 256 threads
    __shared__ float ps[RR];
    if (tid < RR) ps[tid] = p16[(size_t)row * RR + tid];
    __syncthreads();
    for (int n = tid; n < DK; n += 256) {
        float acc = bgk2[n];
#pragma unroll
        for (int r = 0; r < RR; r++) acc += ps[r] * Wgk2[r * DK + n];
        float x = acc;
        float ls = fminf(x, 0.f) - log1pf(expf(-fabsf(x)));
        glog[(size_t)row * DK + n] = ls / GLNORM;
    }
}

// ---------------- GLA precompute (in-place: q->qe, k->kexp, glog->kd) ----------------
__global__ void gla_pre_kernel(float* __restrict__ q, float* __restrict__ k,
                               float* __restrict__ glog,
                               float* __restrict__ ebl) {
    int cid = blockIdx.x;                       // (b*NH + h)*NC + n
    int n = cid % NC;
    int hh = (cid / NC) % NH;
    int b = cid / (NC * NH);
    int d = threadIdx.x;                        // 128
    __shared__ float bsm[CHK * DKH];
    int base = b * TT + n * CHK;
    int col = hh * DKH + d;
    float bs = 0.f;
    for (int c = 0; c < CHK; c++) {
        bs += glog[(size_t)(base + c) * DK + col];
        bsm[c * DKH + d] = bs;
    }
    float blast = bs;
    ebl[(size_t)cid * DKH + d] = expf(blast);
    for (int c = 0; c < CHK; c++) {
        float bb = bsm[c * DKH + d];
        size_t idx = (size_t)(base + c) * DK + col;
        float qv = q[idx], kv = k[idx];
        q[idx]    = qv * expf(bb) * GSCALE;      // qe
        k[idx]    = kv * expf(-bb);              // kexp
        glog[idx] = kv * expf(blast - bb);       // kd
    }
}

// ---------------- GLA intra-chunk: A = tril(qe kexp^T); o = A v ----------------
__global__ void __launch_bounds__(256)
gla_intra_kernel(const float* __restrict__ qe, const float* __restrict__ ke,
                 const float* __restrict__ v, float* __restrict__ o) {
    extern __shared__ float sm[];
    float* qs = sm;                 // 64*128
    float* ks = sm + CHK * DKH;     // 64*128
    float* Am = ks + CHK * DKH;     // 64*64
    int cid = blockIdx.x;
    int n = cid % NC;
    int hh = (cid / NC) % NH;
    int b = cid / (NC * NH);
    int tid = threadIdx.x;          // 256
    int base = b * TT + n * CHK;
    int colb = hh * DKH;
#pragma unroll
    for (int i = 0; i < 8; i++) {
        int idx4 = tid + i * 256;
        int c = idx4 >> 5;
        int d4 = idx4 & 31;
        *(float4*)(qs + c * DKH + d4 * 4) =
            *(const float4*)(qe + (size_t)(base + c) * DK + colb + d4 * 4);
        *(float4*)(ks + c * DKH + d4 * 4) =
            *(const float4*)(ke + (size_t)(base + c) * DK + colb + d4 * 4);
    }
    __syncthreads();
#pragma unroll
    for (int i = 0; i < 16; i++) {
        int idx = tid + i * 256;
        int c = idx >> 6;
        int s = idx & 63;
        float a = 0.f;
        if (s <= c) {
#pragma unroll 8
            for (int d = 0; d < DKH; d++) a += qs[c * DKH + d] * ks[s * DKH + d];
        }
        Am[c * CHK + s] = a;
    }
    __syncthreads();
    float accv[CHK];
#pragma unroll
    for (int c = 0; c < CHK; c++) accv[c] = 0.f;
    int gcol = hh * DVH + tid;
    for (int s = 0; s < CHK; s++) {
        float vv = v[(size_t)(base + s) * DV + gcol];
#pragma unroll
        for (int c = 0; c < CHK; c++) accv[c] += Am[c * CHK + s] * vv;
    }
#pragma unroll
    for (int c = 0; c < CHK; c++) o[(size_t)(base + c) * DV + gcol] = accv[c];
}

// ---------------- GLA inter-chunk scan ----------------
constexpr int NSL = 16;
constexpr int SLW = DVH / NSL;
__global__ void __launch_bounds__(128)
gla_scan_kernel(const float* __restrict__ qe, const float* __restrict__ kd,
                const float* __restrict__ v, const float* __restrict__ ebl,
                float* __restrict__ o) {
    extern __shared__ float sm[];
    float* qs  = sm;
    float* kds = qs + CHK * DKH;
    float* vs  = kds + CHK * DKH;
    float* S   = vs + CHK * SLW;
    float* eb  = S + DKH * SLW;
    int bi = blockIdx.x;
    int sl = bi % NSL;
    int bh = bi / NSL;
    int hh = bh % NH;
    int b  = bh / NH;
    int tid = threadIdx.x;
    for (int i = tid; i < DKH * SLW; i += 128) S[i] = 0.f;
    int e0 = hh * DVH + sl * SLW;
    for (int n = 0; n < NC; n++) {
        int cid = (b * NH + hh) * NC + n;
        int base = b * TT + n * CHK;
        int colb = hh * DKH;
#pragma unroll
        for (int i = 0; i < 16; i++) {
            int idx4 = tid + i * 128;
            int c = idx4 >> 5;
            int d4 = idx4 & 31;
            *(float4*)(qs + c * DKH + d4 * 4) =
                *(const float4*)(qe + (size_t)(base + c) * DK + colb + d4 * 4);
            *(float4*)(kds + c * DKH + d4 * 4) =
                *(const float4*)(kd + (size_t)(base + c) * DK + colb + d4 * 4);
        }
#pragma unroll
        for (int i = 0; i < 8; i++) {
            int idx = tid + i * 128;
            int c = idx / SLW;
            int e = idx % SLW;
            vs[idx] = v[(size_t)(base + c) * DV + e0 + e];
        }
        eb[tid] = ebl[(size_t)cid * DKH + tid];
        __syncthreads();
#pragma unroll
        for (int i = 0; i < 8; i++) {
            int idx = tid + i * 128;
            int c = idx / SLW;
            int e = idx % SLW;
            float a = 0.f;
#pragma unroll 8
            for (int d = 0; d < DKH; d++) a += qs[c * DKH + d] * S[d * SLW + e];
            size_t oi = (size_t)(base + c) * DV + e0 + e;
            o[oi] += a;
        }
        __syncthreads();
#pragma unroll
        for (int i = 0; i < 16; i++) {
            int idx = tid + i * 128;
            int d = idx / SLW;
            int e = idx % SLW;
            float s = S[idx] * eb[d];
#pragma unroll 8
            for (int c = 0; c < CHK; c++) s += kds[c * DKH + d] * vs[c * SLW + e];
            S[idx] = s;
        }
        __syncthreads();
    }
}

// ---------------- gated head-RMSNorm (in place) ----------------
__global__ void gate_kernel(float* __restrict__ o, const float* __restrict__ gout,
                            const float* __restrict__ gw) {
    int bi = blockIdx.x;
    int bt = bi >> 2;
    int hh = bi & 3;
    int e = threadIdx.x;            // 256
    size_t idx = (size_t)bt * DV + hh * DVH + e;
    float ov = o[idx];
    float tot = block_reduce_sum(ov * ov);
    float sc = rsqrtf(tot / (float)DVH + GEPS);
    float g = gout[idx];
    o[idx] = ov * sc * gw[e] * (g / (1.f + expf(-g)));
}

// ---------------- host orchestration ----------------
static void launch_tgemm(int epi, const float* A, const float* B, float* C,
                         const float* aux, int M, int N, int K) {
    dim3 grid(N / 128, M / 128);
    if (epi == 0)      tgemm_kernel<0><<<grid, 256, TG_SMEM>>>(A, B, C, aux, M, N, K);
    else if (epi == 1) tgemm_kernel<1><<<grid, 256, TG_SMEM>>>(A, B, C, aux, M, N, K);
    else               tgemm_kernel<2><<<grid, 256, TG_SMEM>>>(A, B, C, aux, M, N, K);
}

extern "C" void kernel_launch(void* const* d_in, const int* in_sizes, int n_in,
                              void* d_out, int out_size) {
    const float* x      = (const float*)d_in[0];
    const float* anw    = (const float*)d_in[1];
    const float* Wq     = (const float*)d_in[2];
    const float* Wk     = (const float*)d_in[3];
    const float* Wv     = (const float*)d_in[4];
    const float* Wg     = (const float*)d_in[5];
    const float* Wgk1   = (const float*)d_in[6];
    const float* Wgk2   = (const float*)d_in[7];
    const float* bgk2   = (const float*)d_in[8];
    const float* gnw    = (const float*)d_in[9];
    const float* Wo     = (const float*)d_in[10];
    const float* mnw    = (const float*)d_in[11];
    const float* Wgate  = (const float*)d_in[12];
    const float* Wup    = (const float*)d_in[13];
    const float* Wdown  = (const float*)d_in[14];
    float* out = (float*)d_out;

    float *h, *q, *k, *v, *gout, *p16, *glog, *ebl, *o, *x2, *t1;
    cudaGetSymbolAddress((void**)&h,    g_h);
    cudaGetSymbolAddress((void**)&q,    g_q);
    cudaGetSymbolAddress((void**)&k,    g_k);
    cudaGetSymbolAddress((void**)&v,    g_v);
    cudaGetSymbolAddress((void**)&gout, g_gout);
    cudaGetSymbolAddress((void**)&p16,  g_p16);
    cudaGetSymbolAddress((void**)&glog, g_glog);
    cudaGetSymbolAddress((void**)&ebl,  g_ebl);
    cudaGetSymbolAddress((void**)&o,    g_o);
    cudaGetSymbolAddress((void**)&x2,   g_x2);
    cudaGetSymbolAddress((void**)&t1,   g_t1);

    // Aliases (documented in-place reuse)
    float* qe   = q;
    float* kexp = k;
    float* kd   = glog;
    float* og   = o;
    float* nb   = h;
    float* t2   = t1;

    int intra_smem = (CHK * DKH * 2 + CHK * CHK) * 4;                      // 81920 B
    int scan_smem  = (CHK * DKH * 2 + CHK * SLW + DKH * SLW + DKH) * 4;    // 78336 B
    cudaFuncSetAttribute(gla_intra_kernel, cudaFuncAttributeMaxDynamicSharedMemorySize, intra_smem);
    cudaFuncSetAttribute(gla_scan_kernel,  cudaFuncAttributeMaxDynamicSharedMemorySize, scan_smem);
    cudaFuncSetAttribute(tgemm_kernel<0>, cudaFuncAttributeMaxDynamicSharedMemorySize, TG_SMEM);
    cudaFuncSetAttribute(tgemm_kernel<1>, cudaFuncAttributeMaxDynamicSharedMemorySize, TG_SMEM);
    cudaFuncSetAttribute(tgemm_kernel<2>, cudaFuncAttributeMaxDynamicSharedMemorySize, TG_SMEM);

    // 1) attn norm
    rms_kernel<<<MM, 256>>>(x, anw, h, HS);
    // 2) projections (tf32 tensor cores)
    launch_tgemm(0, h, Wq, q,    nullptr, MM, DK, HS);
    launch_tgemm(0, h, Wk, k,    nullptr, MM, DK, HS);
    launch_tgemm(0, h, Wv, v,    nullptr, MM, DV, HS);
    launch_tgemm(0, h, Wg, gout, nullptr, MM, DV, HS);
    // 3) gate logits (low rank)
    p16_kernel<<<MM, 128>>>(h, Wgk1, p16);
    glog_kernel<<<MM, 256>>>(p16, Wgk2, bgk2, glog);
    // 4) GLA (gla_pre converts q->qe, k->kexp, glog->kd in place)
    gla_pre_kernel<<<BB * NH * NC, DKH>>>(q, k, glog, ebl);
    gla_intra_kernel<<<BB * NH * NC, 256, intra_smem>>>(qe, kexp, v, o);
    gla_scan_kernel<<<BB * NH * NSL, DKH, scan_smem>>>(qe, kd, v, ebl, o);
    // 5) gated head norm (o -> og in place)
    gate_kernel<<<MM * NH, DVH>>>(o, gout, gnw);
    // 6) output projection + residual -> x2
    launch_tgemm(1, og, Wo, x2, x, MM, HS, DV);
    // 7) MLP (nb aliases h; t2 aliases t1)
    rms_kernel<<<MM, 256>>>(x2, mnw, nb, HS);
    launch_tgemm(0, nb, Wgate, t1, nullptr, MM, IM, HS);
    launch_tgemm(2, nb, Wup,   t2, t1,      MM, IM, HS);   // t2 = silu(t1) * (nb@Wup)
    launch_tgemm(1, t2, Wdown, out, x2,     MM, HS, IM);   // out = x2 + t2@Wdown
}